// round 5
// baseline (speedup 1.0000x reference)
#include <cuda_runtime.h>
#include <math_constants.h>

#define B_  8
#define LQ_ 2048
#define LK_ 2048
#define D_  128
#define E_  64

// Scratch for projected q, k, v (fp32). 3 x 4 MB, static device arrays (no alloc).
__device__ float g_q[B_ * LQ_ * E_];
__device__ float g_k[B_ * LK_ * E_];
__device__ float g_v[B_ * LK_ * E_];

// ---------------------------------------------------------------------------
// Projection kernel: out[row, 0:64] = X[row, 0:128] @ W[128, 64]
// grid: (128, 3): x = row tile of 128, y selects (q | k | v)
// 256 threads, thread (tx=tid&15, ty=tid>>4) computes 8 rows x 4 cols.
// ---------------------------------------------------------------------------
#define PROJ_SMEM_BYTES ((128 * 132 + 128 * 68) * 4)

__global__ __launch_bounds__(256, 1) void proj_kernel(
    const float* __restrict__ query,
    const float* __restrict__ key,
    const float* __restrict__ Wq,
    const float* __restrict__ Wk,
    const float* __restrict__ Wv)
{
    extern __shared__ float smem[];
    float* sX = smem;             // [128][132]  (row pad 4 floats)
    float* sW = smem + 128 * 132; // [128][68]

    const float* X;
    const float* W;
    float* out;
    if (blockIdx.y == 0)      { X = query; W = Wq; out = g_q; }
    else if (blockIdx.y == 1) { X = key;   W = Wk; out = g_k; }
    else                      { X = key;   W = Wv; out = g_v; }

    const int tid = threadIdx.x;
    const int tx = tid & 15;
    const int ty = tid >> 4;
    const int row0 = blockIdx.x * 128;

    // Load W: 128x64 floats = 2048 float4
    for (int i = tid; i < 128 * 16; i += 256) {
        int r = i >> 4, c4 = i & 15;
        float4 w = ((const float4*)(W + r * 64))[c4];
        *(float4*)(sW + r * 68 + c4 * 4) = w;
    }
    // Load X tile: 128x128 floats = 4096 float4
    for (int i = tid; i < 128 * 32; i += 256) {
        int r = i >> 5, c4 = i & 31;
        float4 x = ((const float4*)(X + (size_t)(row0 + r) * D_))[c4];
        *(float4*)(sX + r * 132 + c4 * 4) = x;
    }
    __syncthreads();

    float acc[8][4];
#pragma unroll
    for (int i = 0; i < 8; i++)
#pragma unroll
        for (int j = 0; j < 4; j++) acc[i][j] = 0.0f;

    for (int k = 0; k < 128; k += 4) {
        float4 xv[8];
#pragma unroll
        for (int i = 0; i < 8; i++)
            xv[i] = *(float4*)(sX + (ty + 16 * i) * 132 + k);
#pragma unroll
        for (int kk = 0; kk < 4; kk++) {
            float4 wv = *(float4*)(sW + (k + kk) * 68 + tx * 4);
#pragma unroll
            for (int i = 0; i < 8; i++) {
                float a = ((const float*)&xv[i])[kk];
                acc[i][0] += a * wv.x;
                acc[i][1] += a * wv.y;
                acc[i][2] += a * wv.z;
                acc[i][3] += a * wv.w;
            }
        }
    }

#pragma unroll
    for (int i = 0; i < 8; i++) {
        float4 r4 = make_float4(acc[i][0], acc[i][1], acc[i][2], acc[i][3]);
        *(float4*)(out + (size_t)(row0 + ty + 16 * i) * E_ + tx * 4) = r4;
    }
}

// ---------------------------------------------------------------------------
// Flash attention kernel.
// grid: (16, 8): x = q tile (128 rows), y = batch. 256 threads.
// Thread (tx, ty): S tile 8 rows x 8 cols (cols = {tx*4..+3, 64+tx*4..+3}),
//                  O tile 8 rows x 4 cols (cols = tx*4..+3).
// Smem: Q[128][68], Kt[64][132] (transposed), V[128][68], P[128][132].
// ---------------------------------------------------------------------------
#define FLASH_SMEM_BYTES ((128 * 68 + 64 * 132 + 128 * 68 + 128 * 132) * 4)

__global__ __launch_bounds__(256, 1) void flash_kernel(float* __restrict__ out)
{
    extern __shared__ float smem[];
    float* sQ  = smem;                  // [128][68]
    float* sKt = sQ + 128 * 68;         // [64][132]
    float* sV  = sKt + 64 * 132;        // [128][68]
    float* sP  = sV + 128 * 68;         // [128][132]

    const int tid = threadIdx.x;
    const int tx = tid & 15;
    const int ty = tid >> 4;
    const int b = blockIdx.y;
    const int q0 = blockIdx.x * 128;

    const float* qptr = g_q + ((size_t)b * LQ_ + q0) * E_;
    const float* kptr = g_k + (size_t)b * LK_ * E_;
    const float* vptr = g_v + (size_t)b * LK_ * E_;

    // Load Q tile: 128x64 floats = 2048 float4 (stays resident)
    for (int i = tid; i < 2048; i += 256) {
        int r = i >> 4, c4 = i & 15;
        *(float4*)(sQ + r * 68 + c4 * 4) = ((const float4*)(qptr + r * E_))[c4];
    }

    float o[8][4];
    float mrow[8], lrow[8];
#pragma unroll
    for (int i = 0; i < 8; i++) {
        mrow[i] = -CUDART_INF_F;
        lrow[i] = 0.0f;
#pragma unroll
        for (int j = 0; j < 4; j++) o[i][j] = 0.0f;
    }

    for (int kt = 0; kt < LK_ / 128; kt++) {
        const float* kp = kptr + (size_t)kt * 128 * E_;
        const float* vp = vptr + (size_t)kt * 128 * E_;

        __syncthreads();  // previous tile's PV reads of sV/sP done

        // Load V tile [key][e]
        for (int i = tid; i < 2048; i += 256) {
            int r = i >> 4, c4 = i & 15;
            *(float4*)(sV + r * 68 + c4 * 4) = ((const float4*)(vp + r * E_))[c4];
        }
        // Load K tile transposed: sKt[e][key]
        for (int i = tid; i < 2048; i += 256) {
            int keyr = i >> 4, c4 = i & 15;
            float4 kv = ((const float4*)(kp + keyr * E_))[c4];
            sKt[(c4 * 4 + 0) * 132 + keyr] = kv.x;
            sKt[(c4 * 4 + 1) * 132 + keyr] = kv.y;
            sKt[(c4 * 4 + 2) * 132 + keyr] = kv.z;
            sKt[(c4 * 4 + 3) * 132 + keyr] = kv.w;
        }
        __syncthreads();

        // S = Q @ K^T : per-thread 8x8
        float s[8][8];
#pragma unroll
        for (int i = 0; i < 8; i++)
#pragma unroll
            for (int j = 0; j < 8; j++) s[i][j] = 0.0f;

        for (int e = 0; e < E_; e += 4) {
            float4 qv[8];
#pragma unroll
            for (int i = 0; i < 8; i++)
                qv[i] = *(float4*)(sQ + (ty + 16 * i) * 68 + e);
#pragma unroll
            for (int ee = 0; ee < 4; ee++) {
                float4 k0 = *(float4*)(sKt + (e + ee) * 132 + tx * 4);
                float4 k1 = *(float4*)(sKt + (e + ee) * 132 + 64 + tx * 4);
#pragma unroll
                for (int i = 0; i < 8; i++) {
                    float a = ((const float*)&qv[i])[ee];
                    s[i][0] += a * k0.x; s[i][1] += a * k0.y;
                    s[i][2] += a * k0.z; s[i][3] += a * k0.w;
                    s[i][4] += a * k1.x; s[i][5] += a * k1.y;
                    s[i][6] += a * k1.z; s[i][7] += a * k1.w;
                }
            }
        }

        // Online softmax (rows split across 16 tx lanes; shfl-xor within 16-lane groups)
#pragma unroll
        for (int i = 0; i < 8; i++) {
            float m = s[i][0];
#pragma unroll
            for (int j = 1; j < 8; j++) m = fmaxf(m, s[i][j]);
#pragma unroll
            for (int off = 1; off < 16; off <<= 1)
                m = fmaxf(m, __shfl_xor_sync(0xffffffffu, m, off));
            float mnew = fmaxf(mrow[i], m);
            float corr = __expf(mrow[i] - mnew);  // 0 on first tile (-inf - finite)
            mrow[i] = mnew;

            float psum = 0.0f;
#pragma unroll
            for (int j = 0; j < 8; j++) {
                float p = __expf(s[i][j] - mnew);
                s[i][j] = p;
                psum += p;
            }
#pragma unroll
            for (int off = 1; off < 16; off <<= 1)
                psum += __shfl_xor_sync(0xffffffffu, psum, off);
            lrow[i] = lrow[i] * corr + psum;
#pragma unroll
            for (int j = 0; j < 4; j++) o[i][j] *= corr;

            *(float4*)(sP + (ty + 16 * i) * 132 + tx * 4) =
                make_float4(s[i][0], s[i][1], s[i][2], s[i][3]);
            *(float4*)(sP + (ty + 16 * i) * 132 + 64 + tx * 4) =
                make_float4(s[i][4], s[i][5], s[i][6], s[i][7]);
        }
        __syncthreads();  // P fully written

        // O += P @ V : per-thread 8x4
        for (int k = 0; k < 128; k += 4) {
            float4 pv[8];
#pragma unroll
            for (int i = 0; i < 8; i++)
                pv[i] = *(float4*)(sP + (ty + 16 * i) * 132 + k);
#pragma unroll
            for (int kk = 0; kk < 4; kk++) {
                float4 vv = *(float4*)(sV + (k + kk) * 68 + tx * 4);
#pragma unroll
                for (int i = 0; i < 8; i++) {
                    float p = ((const float*)&pv[i])[kk];
                    o[i][0] += p * vv.x;
                    o[i][1] += p * vv.y;
                    o[i][2] += p * vv.z;
                    o[i][3] += p * vv.w;
                }
            }
        }
    }

    // Normalize and write out
    float* op = out + ((size_t)b * LQ_ + q0) * E_;
#pragma unroll
    for (int i = 0; i < 8; i++) {
        float inv = 1.0f / lrow[i];
        float4 r4 = make_float4(o[i][0] * inv, o[i][1] * inv,
                                o[i][2] * inv, o[i][3] * inv);
        *(float4*)(op + (size_t)(ty + 16 * i) * E_ + tx * 4) = r4;
    }
}

// ---------------------------------------------------------------------------
extern "C" void kernel_launch(void* const* d_in, const int* in_sizes, int n_in,
                              void* d_out, int out_size)
{
    const float* query = (const float*)d_in[0];
    const float* key   = (const float*)d_in[1];
    const float* Wq    = (const float*)d_in[2];
    const float* Wk    = (const float*)d_in[3];
    const float* Wv    = (const float*)d_in[4];

    cudaFuncSetAttribute(proj_kernel, cudaFuncAttributeMaxDynamicSharedMemorySize,
                         PROJ_SMEM_BYTES);
    cudaFuncSetAttribute(flash_kernel, cudaFuncAttributeMaxDynamicSharedMemorySize,
                         FLASH_SMEM_BYTES);

    dim3 gp(128, 3);
    proj_kernel<<<gp, 256, PROJ_SMEM_BYTES>>>(query, key, Wq, Wk, Wv);

    dim3 gf(LQ_ / 128, B_);
    flash_kernel<<<gf, 256, FLASH_SMEM_BYTES>>>((float*)d_out);
}